// round 2
// baseline (speedup 1.0000x reference)
#include <cuda_runtime.h>
#include <cuda_bf16.h>
#include <math.h>

// Problem constants (fixed shapes)
#define NND   50000          // nodes
#define NPAD  50048          // padded to multiple of 64 for GEMM tiles
#define EE    800000         // edges
#define ET    (EE + NND)     // edges + self loops = 850000
#define GG    512            // graphs
#define FIN   128
#define HID   128
#define HEADS 4
#define D1    512            // HEADS*HID

// ---------------- scratch (device globals; no allocs allowed) ----------------
__device__ __align__(128) float    g_h1[(size_t)NPAD * D1];     // x@W1
__device__ __align__(128) float    g_out1[(size_t)NPAD * D1];   // layer1 aggregate -> elu -> gemm2 input
__device__ __align__(128) float    g_h2[(size_t)NPAD * HID];    // h1a@W2
__device__ __align__(128) float    g_out2[(size_t)NPAD * HID];  // layer2 aggregate
__device__ __align__(128) float    g_as1[NND * HEADS];
__device__ __align__(128) float    g_ad1[NND * HEADS];
__device__ __align__(128) float    g_ev1[(size_t)ET * HEADS];   // logits then exp values
__device__ __align__(128) unsigned g_m1[NND * HEADS];
__device__ __align__(128) float    g_den1[NND * HEADS];
__device__ __align__(128) float    g_as2[NND];
__device__ __align__(128) float    g_ad2[NND];
__device__ __align__(128) float    g_ev2[ET];
__device__ __align__(128) unsigned g_m2[NND];
__device__ __align__(128) float    g_den2[NND];
__device__ __align__(128) float    g_pool[GG * HID];
__device__ __align__(128) float    g_cnt[GG];

// ---------------- helpers ----------------
__device__ __forceinline__ unsigned f2o(float f) {
    unsigned u = __float_as_uint(f);
    return (u & 0x80000000u) ? ~u : (u | 0x80000000u);
}
__device__ __forceinline__ float o2f(unsigned u) {
    return (u & 0x80000000u) ? __uint_as_float(u ^ 0x80000000u) : __uint_as_float(~u);
}
__device__ __forceinline__ float lrelu(float x) { return x > 0.f ? x : 0.2f * x; }
__device__ __forceinline__ float elu(float x)   { return x > 0.f ? x : expf(x) - 1.f; }
__device__ __forceinline__ float wred(float v) {
#pragma unroll
    for (int o = 16; o > 0; o >>= 1) v += __shfl_xor_sync(0xffffffffu, v, o);
    return v;
}

// ---------------- zero kernels ----------------
__global__ void zero_big() {
    size_t i = (size_t)blockIdx.x * blockDim.x + threadIdx.x;
    float4 z = make_float4(0.f, 0.f, 0.f, 0.f);
    if (i < (size_t)NPAD * D1 / 4)  ((float4*)g_out1)[i] = z;
    if (i < (size_t)NPAD * HID / 4) ((float4*)g_out2)[i] = z;
}
__global__ void zero_small() {
    int i = blockIdx.x * blockDim.x + threadIdx.x;
    float4 z = make_float4(0.f, 0.f, 0.f, 0.f);
    if (i < NND * HEADS / 4) { ((float4*)g_m1)[i] = z; ((float4*)g_den1)[i] = z; }
    if (i < NND / 4)         { ((float4*)g_m2)[i] = z; ((float4*)g_den2)[i] = z; }
    if (i < GG * HID / 4)    ((float4*)g_pool)[i] = z;
    if (i < GG / 4)          ((float4*)g_cnt)[i] = z;
}

// ---------------- SGEMM: C[M,N] = A[M,K] @ B[K,N] (row-major) ----------------
#define BM 64
#define BN 64
#define BK 16
__global__ __launch_bounds__(256) void sgemm(const float* __restrict__ A,
                                             const float* __restrict__ B,
                                             float* __restrict__ C,
                                             int M, int N, int K) {
    __shared__ float As[BK][BM];
    __shared__ float Bs[BK][BN];
    int tid = threadIdx.x;
    int rowBlock = blockIdx.y * BM, colBlock = blockIdx.x * BN;
    int ar = tid >> 2;          // 0..63
    int ac = (tid & 3) * 4;     // 0,4,8,12
    int br = tid >> 4;          // 0..15
    int bc = (tid & 15) * 4;    // 0..60
    int tr = (tid >> 4) * 4;    // thread tile row
    int tc = (tid & 15) * 4;    // thread tile col
    float acc[4][4] = {};
    for (int k0 = 0; k0 < K; k0 += BK) {
        float4 av = make_float4(0.f, 0.f, 0.f, 0.f);
        if (rowBlock + ar < M)
            av = *(const float4*)(A + (size_t)(rowBlock + ar) * K + k0 + ac);
        As[ac + 0][ar] = av.x; As[ac + 1][ar] = av.y;
        As[ac + 2][ar] = av.z; As[ac + 3][ar] = av.w;
        float4 bv = *(const float4*)(B + (size_t)(k0 + br) * N + colBlock + bc);
        *(float4*)&Bs[br][bc] = bv;
        __syncthreads();
#pragma unroll
        for (int kk = 0; kk < BK; kk++) {
            float a[4], b[4];
#pragma unroll
            for (int i = 0; i < 4; i++) a[i] = As[kk][tr + i];
#pragma unroll
            for (int j = 0; j < 4; j++) b[j] = Bs[kk][tc + j];
#pragma unroll
            for (int i = 0; i < 4; i++)
#pragma unroll
                for (int j = 0; j < 4; j++) acc[i][j] += a[i] * b[j];
        }
        __syncthreads();
    }
#pragma unroll
    for (int i = 0; i < 4; i++) {
        int r = rowBlock + tr + i;
        if (r < M)
            *(float4*)(C + (size_t)r * N + colBlock + tc) =
                make_float4(acc[i][0], acc[i][1], acc[i][2], acc[i][3]);
    }
}

// ---------------- attention scores ----------------
// Layer 1: block per node, warp w handles head w
__global__ void scores1(const float* __restrict__ a_src, const float* __restrict__ a_dst) {
    int n = blockIdx.x;
    int w = threadIdx.x >> 5, l = threadIdx.x & 31;
    const float4* hp = (const float4*)(g_h1 + (size_t)n * D1 + w * HID);
    const float4* ap = (const float4*)(a_src + w * HID);
    const float4* dp = (const float4*)(a_dst + w * HID);
    float4 h = hp[l], a = ap[l], d = dp[l];
    float s = h.x * a.x + h.y * a.y + h.z * a.z + h.w * a.w;
    float t = h.x * d.x + h.y * d.y + h.z * d.z + h.w * d.w;
    s = wred(s); t = wred(t);
    if (l == 0) { g_as1[n * HEADS + w] = s; g_ad1[n * HEADS + w] = t; }
}
// Layer 2: warp per node (heads=1)
__global__ void scores2(const float* __restrict__ a_src, const float* __restrict__ a_dst) {
    int gw = (blockIdx.x * blockDim.x + threadIdx.x) >> 5;
    int l = threadIdx.x & 31;
    if (gw >= NND) return;
    float4 h = ((const float4*)g_h2)[(size_t)gw * 32 + l];
    float4 a = ((const float4*)a_src)[l];
    float4 d = ((const float4*)a_dst)[l];
    float s = h.x * a.x + h.y * a.y + h.z * a.z + h.w * a.w;
    float t = h.x * d.x + h.y * d.y + h.z * d.z + h.w * d.w;
    s = wred(s); t = wred(t);
    if (l == 0) { g_as2[gw] = s; g_ad2[gw] = t; }
}

// ---------------- edge softmax passes, layer 1 ----------------
__global__ void edge_logits1(const int* __restrict__ src, const int* __restrict__ dst) {
    int e = blockIdx.x * blockDim.x + threadIdx.x;
    if (e >= ET) return;
    int s = e < EE ? src[e] : e - EE;
    int d = e < EE ? dst[e] : e - EE;
    float4 a = ((const float4*)g_as1)[s];
    float4 b = ((const float4*)g_ad1)[d];
    float4 lg = make_float4(lrelu(a.x + b.x), lrelu(a.y + b.y),
                            lrelu(a.z + b.z), lrelu(a.w + b.w));
    ((float4*)g_ev1)[e] = lg;
    atomicMax(&g_m1[d * 4 + 0], f2o(lg.x));
    atomicMax(&g_m1[d * 4 + 1], f2o(lg.y));
    atomicMax(&g_m1[d * 4 + 2], f2o(lg.z));
    atomicMax(&g_m1[d * 4 + 3], f2o(lg.w));
}
__global__ void edge_exp1(const int* __restrict__ src, const int* __restrict__ dst) {
    int e = blockIdx.x * blockDim.x + threadIdx.x;
    if (e >= ET) return;
    int d = e < EE ? dst[e] : e - EE;
    float4 lg = ((const float4*)g_ev1)[e];
    uint4 m = ((const uint4*)g_m1)[d];
    float4 ev = make_float4(expf(lg.x - o2f(m.x)), expf(lg.y - o2f(m.y)),
                            expf(lg.z - o2f(m.z)), expf(lg.w - o2f(m.w)));
    ((float4*)g_ev1)[e] = ev;
    atomicAdd((float4*)&g_den1[d * 4], ev);
}
// One warp per edge: out1[dst] += alpha * h1[src]  (512 floats, float4 RED)
__global__ void agg1(const int* __restrict__ src, const int* __restrict__ dst) {
    int gw = (blockIdx.x * blockDim.x + threadIdx.x) >> 5;
    if (gw >= ET) return;
    int l = threadIdx.x & 31;
    int s = gw < EE ? src[gw] : gw - EE;
    int d = gw < EE ? dst[gw] : gw - EE;
    float4 ev = ((const float4*)g_ev1)[gw];
    float4 dn = ((const float4*)g_den1)[d];
    float al[4] = {ev.x / dn.x, ev.y / dn.y, ev.z / dn.z, ev.w / dn.w};
    const float4* hs = (const float4*)(g_h1 + (size_t)s * D1);
    float4* od = (float4*)(g_out1 + (size_t)d * D1);
#pragma unroll
    for (int k = 0; k < 4; k++) {
        float4 v = hs[l + 32 * k];
        float a = al[k];
        atomicAdd(od + l + 32 * k, make_float4(v.x * a, v.y * a, v.z * a, v.w * a));
    }
}
// out1 = elu(out1 + b1)
__global__ void finalize1(const float* __restrict__ b1) {
    int i = blockIdx.x * blockDim.x + threadIdx.x;
    if (i >= NND * D1 / 4) return;
    int c4 = i & (D1 / 4 - 1);
    float4 v = ((float4*)g_out1)[i];
    float4 b = ((const float4*)b1)[c4];
    v.x = elu(v.x + b.x); v.y = elu(v.y + b.y);
    v.z = elu(v.z + b.z); v.w = elu(v.w + b.w);
    ((float4*)g_out1)[i] = v;
}

// ---------------- edge softmax passes, layer 2 (heads=1) ----------------
__global__ void edge_logits2(const int* __restrict__ src, const int* __restrict__ dst) {
    int e = blockIdx.x * blockDim.x + threadIdx.x;
    if (e >= ET) return;
    int s = e < EE ? src[e] : e - EE;
    int d = e < EE ? dst[e] : e - EE;
    float lg = lrelu(g_as2[s] + g_ad2[d]);
    g_ev2[e] = lg;
    atomicMax(&g_m2[d], f2o(lg));
}
__global__ void edge_exp2(const int* __restrict__ src, const int* __restrict__ dst) {
    int e = blockIdx.x * blockDim.x + threadIdx.x;
    if (e >= ET) return;
    int d = e < EE ? dst[e] : e - EE;
    float ev = expf(g_ev2[e] - o2f(g_m2[d]));
    g_ev2[e] = ev;
    atomicAdd(&g_den2[d], ev);
}
__global__ void agg2(const int* __restrict__ src, const int* __restrict__ dst) {
    int gw = (blockIdx.x * blockDim.x + threadIdx.x) >> 5;
    if (gw >= ET) return;
    int l = threadIdx.x & 31;
    int s = gw < EE ? src[gw] : gw - EE;
    int d = gw < EE ? dst[gw] : gw - EE;
    float a = g_ev2[gw] / g_den2[d];
    float4 v = ((const float4*)g_h2)[(size_t)s * 32 + l];
    atomicAdd(((float4*)(g_out2 + (size_t)d * HID)) + l,
              make_float4(v.x * a, v.y * a, v.z * a, v.w * a));
}

// ---------------- pooling + output ----------------
__global__ void pool_kernel(const int* __restrict__ batch, const float* __restrict__ b2) {
    int n = blockIdx.x, t = threadIdx.x;
    int g = batch[n];
    float v = elu(g_out2[(size_t)n * HID + t] + b2[t]);
    atomicAdd(&g_pool[g * HID + t], v);
    if (t == 0) atomicAdd(&g_cnt[g], 1.0f);
}
__global__ void final_kernel(const float* __restrict__ Wl, const float* __restrict__ bl,
                             float* __restrict__ out) {
    int gw = (blockIdx.x * blockDim.x + threadIdx.x) >> 5;
    int l = threadIdx.x & 31;
    if (gw >= GG) return;
    float4 p = ((const float4*)g_pool)[gw * 32 + l];
    float4 w = ((const float4*)Wl)[l];
    float s = p.x * w.x + p.y * w.y + p.z * w.z + p.w * w.w;
    s = wred(s);
    if (l == 0) out[gw] = s / fmaxf(g_cnt[gw], 1.0f) + bl[0];
}

// ---------------- launch ----------------
extern "C" void kernel_launch(void* const* d_in, const int* in_sizes, int n_in,
                              void* d_out, int out_size) {
    const float* x   = (const float*)d_in[0];
    const int*   ei  = (const int*)d_in[1];
    const int*   bat = (const int*)d_in[2];
    const float* W1  = (const float*)d_in[3];
    const float* as1 = (const float*)d_in[4];
    const float* ad1 = (const float*)d_in[5];
    const float* b1  = (const float*)d_in[6];
    const float* W2  = (const float*)d_in[7];
    const float* as2 = (const float*)d_in[8];
    const float* ad2 = (const float*)d_in[9];
    const float* b2  = (const float*)d_in[10];
    const float* Wl  = (const float*)d_in[11];
    const float* bl  = (const float*)d_in[12];
    float* out = (float*)d_out;
    const int* src = ei;
    const int* dst = ei + EE;

    float *p_h1, *p_out1, *p_h2;
    cudaGetSymbolAddress((void**)&p_h1, g_h1);
    cudaGetSymbolAddress((void**)&p_out1, g_out1);
    cudaGetSymbolAddress((void**)&p_h2, g_h2);

    int zb = (int)(((size_t)NPAD * D1 / 4 + 255) / 256);
    zero_big<<<zb, 256>>>();
    zero_small<<<(NND * HEADS / 4 + 255) / 256, 256>>>();

    // Layer 1
    sgemm<<<dim3(D1 / BN, (NND + BM - 1) / BM), 256>>>(x, W1, p_h1, NND, D1, FIN);
    scores1<<<NND, 128>>>(as1, ad1);
    int eb = (ET + 255) / 256;
    edge_logits1<<<eb, 256>>>(src, dst);
    edge_exp1<<<eb, 256>>>(src, dst);
    agg1<<<(ET + 7) / 8, 256>>>(src, dst);
    finalize1<<<(NND * D1 / 4 + 255) / 256, 256>>>(b1);

    // Layer 2
    sgemm<<<dim3(HID / BN, (NND + BM - 1) / BM), 256>>>(p_out1, W2, p_h2, NND, HID, D1);
    scores2<<<(NND * 32 + 127) / 128, 128>>>(as2, ad2);
    edge_logits2<<<eb, 256>>>(src, dst);
    edge_exp2<<<eb, 256>>>(src, dst);
    agg2<<<(ET + 7) / 8, 256>>>(src, dst);

    // Pool + linear head
    pool_kernel<<<NND, 128>>>(bat, b2);
    final_kernel<<<(GG * 32 + 255) / 256, 256>>>(Wl, bl, out);
}

// round 4
// speedup vs baseline: 1.6614x; 1.6614x over previous
#include <cuda_runtime.h>
#include <cuda_bf16.h>
#include <math.h>

#define NND   50000
#define NPAD  50048
#define EE    800000
#define ET    (EE + NND)
#define GG    512
#define FIN   128
#define HID   128
#define HEADS 4
#define D1    512

// ---------------- scratch ----------------
__device__ __align__(128) float g_h1[(size_t)NPAD * D1];
__device__ __align__(128) float g_out1[(size_t)NPAD * D1];
__device__ __align__(128) float g_h2[(size_t)NPAD * HID];
__device__ __align__(128) float g_as1[NND * HEADS];
__device__ __align__(128) float g_ad1[NND * HEADS];
__device__ __align__(128) float g_as2[NND];
__device__ __align__(128) float g_ad2[NND];
__device__ __align__(128) float g_pool[GG * HID];
__device__ __align__(128) float g_cnt[GG];
// CSR
__device__ __align__(128) int g_deg[NND];
__device__ __align__(128) int g_rowptr[NND + 1];
__device__ __align__(128) int g_cursor[NND];
__device__ __align__(128) int g_colsrc[ET];
__device__ __align__(128) int g_bsum[128];

// ---------------- helpers ----------------
__device__ __forceinline__ float lrelu(float x) { return x > 0.f ? x : 0.2f * x; }
__device__ __forceinline__ float elu(float x)   { return x > 0.f ? x : __expf(x) - 1.f; }
__device__ __forceinline__ float wsum(float v) {
#pragma unroll
    for (int o = 16; o > 0; o >>= 1) v += __shfl_xor_sync(0xffffffffu, v, o);
    return v;
}
__device__ __forceinline__ float wmax(float v) {
#pragma unroll
    for (int o = 16; o > 0; o >>= 1) v = fmaxf(v, __shfl_xor_sync(0xffffffffu, v, o));
    return v;
}

// ---------------- zero ----------------
__global__ void zero_misc() {
    int i = blockIdx.x * blockDim.x + threadIdx.x;
    if (i < NND) g_deg[i] = 0;
    if (i < GG * HID) g_pool[i] = 0.f;
    if (i < GG) g_cnt[i] = 0.f;
}

// ---------------- CSR build ----------------
__global__ void deg_kernel(const int* __restrict__ dst) {
    int e = blockIdx.x * blockDim.x + threadIdx.x;
    if (e >= ET) return;
    int d = e < EE ? dst[e] : e - EE;
    atomicAdd(&g_deg[d], 1);
}
__global__ void scanA() {
    __shared__ int sm[512];
    int i = blockIdx.x * 512 + threadIdx.x;
    sm[threadIdx.x] = (i < NND) ? g_deg[i] : 0;
    __syncthreads();
#pragma unroll
    for (int o = 1; o < 512; o <<= 1) {
        int t = (threadIdx.x >= o) ? sm[threadIdx.x - o] : 0;
        __syncthreads();
        sm[threadIdx.x] += t;
        __syncthreads();
    }
    if (i < NND) g_rowptr[i + 1] = sm[threadIdx.x];
    if (threadIdx.x == 511) g_bsum[blockIdx.x] = sm[511];
}
__global__ void scanB(int nblk) {
    if (threadIdx.x == 0) {
        int run = 0;
        for (int b = 0; b < nblk; b++) { int t = g_bsum[b]; g_bsum[b] = run; run += t; }
        g_rowptr[0] = 0;
    }
}
__global__ void scanC() {
    int i = blockIdx.x * 512 + threadIdx.x;
    if (i < NND) {
        int v = g_rowptr[i + 1] + g_bsum[blockIdx.x];
        g_rowptr[i + 1] = v;
        g_cursor[i] = v - g_deg[i];   // exclusive start
    }
}
__global__ void scatter_kernel(const int* __restrict__ src, const int* __restrict__ dst) {
    int e = blockIdx.x * blockDim.x + threadIdx.x;
    if (e >= ET) return;
    int s = e < EE ? src[e] : e - EE;
    int d = e < EE ? dst[e] : e - EE;
    int pos = atomicAdd(&g_cursor[d], 1);
    g_colsrc[pos] = s;
}

// ---------------- SGEMM: C[M,N] = A[M,K] @ B[K,N] ----------------
#define BM 64
#define BN 64
#define BK 16
__global__ __launch_bounds__(256) void sgemm(const float* __restrict__ A,
                                             const float* __restrict__ B,
                                             float* __restrict__ C,
                                             int M, int N, int K) {
    __shared__ float As[BK][BM];
    __shared__ float Bs[BK][BN];
    int tid = threadIdx.x;
    int rowBlock = blockIdx.y * BM, colBlock = blockIdx.x * BN;
    int ar = tid >> 2, ac = (tid & 3) * 4;
    int br = tid >> 4, bc = (tid & 15) * 4;
    int tr = (tid >> 4) * 4, tc = (tid & 15) * 4;
    float acc[4][4] = {};
    for (int k0 = 0; k0 < K; k0 += BK) {
        float4 av = make_float4(0.f, 0.f, 0.f, 0.f);
        if (rowBlock + ar < M)
            av = *(const float4*)(A + (size_t)(rowBlock + ar) * K + k0 + ac);
        As[ac + 0][ar] = av.x; As[ac + 1][ar] = av.y;
        As[ac + 2][ar] = av.z; As[ac + 3][ar] = av.w;
        *(float4*)&Bs[br][bc] = *(const float4*)(B + (size_t)(k0 + br) * N + colBlock + bc);
        __syncthreads();
#pragma unroll
        for (int kk = 0; kk < BK; kk++) {
            float a[4], b[4];
#pragma unroll
            for (int i = 0; i < 4; i++) a[i] = As[kk][tr + i];
#pragma unroll
            for (int j = 0; j < 4; j++) b[j] = Bs[kk][tc + j];
#pragma unroll
            for (int i = 0; i < 4; i++)
#pragma unroll
                for (int j = 0; j < 4; j++) acc[i][j] += a[i] * b[j];
        }
        __syncthreads();
    }
#pragma unroll
    for (int i = 0; i < 4; i++) {
        int r = rowBlock + tr + i;
        if (r < M)
            *(float4*)(C + (size_t)r * N + colBlock + tc) =
                make_float4(acc[i][0], acc[i][1], acc[i][2], acc[i][3]);
    }
}

// ---------------- attention scores ----------------
__global__ void scores1(const float* __restrict__ a_src, const float* __restrict__ a_dst) {
    int n = blockIdx.x;
    int w = threadIdx.x >> 5, l = threadIdx.x & 31;
    float4 h = ((const float4*)(g_h1 + (size_t)n * D1 + w * HID))[l];
    float4 a = ((const float4*)(a_src + w * HID))[l];
    float4 d = ((const float4*)(a_dst + w * HID))[l];
    float s = h.x * a.x + h.y * a.y + h.z * a.z + h.w * a.w;
    float t = h.x * d.x + h.y * d.y + h.z * d.z + h.w * d.w;
    s = wsum(s); t = wsum(t);
    if (l == 0) { g_as1[n * HEADS + w] = s; g_ad1[n * HEADS + w] = t; }
}
__global__ void scores2(const float* __restrict__ a_src, const float* __restrict__ a_dst) {
    int gw = (blockIdx.x * blockDim.x + threadIdx.x) >> 5;
    int l = threadIdx.x & 31;
    if (gw >= NND) return;
    float4 h = ((const float4*)g_h2)[(size_t)gw * 32 + l];
    float4 a = ((const float4*)a_src)[l];
    float4 d = ((const float4*)a_dst)[l];
    float s = h.x * a.x + h.y * a.y + h.z * a.z + h.w * a.w;
    float t = h.x * d.x + h.y * d.y + h.z * d.z + h.w * d.w;
    s = wsum(s); t = wsum(t);
    if (l == 0) { g_as2[gw] = s; g_ad2[gw] = t; }
}

// ---------------- fused layer-1 aggregation (block per dst node) ----------------
// Computes softmax over incident edges and out1[d] = elu(sum alpha*h1[src] + b1)
__global__ __launch_bounds__(128) void gat_agg1(const float* __restrict__ b1) {
    int d = blockIdx.x;
    int t = threadIdx.x, w = t >> 5, l = t & 31;
    int beg = g_rowptr[d], end = g_rowptr[d + 1];
    float4 adv = ((const float4*)g_ad1)[d];

    __shared__ float4 s_red[4];
    __shared__ float4 s_bc[2];   // [0]=max, [1]=inv denom

    // pass 1: per-head max
    float4 pm = make_float4(-1e30f, -1e30f, -1e30f, -1e30f);
    for (int i = beg + t; i < end; i += 128) {
        float4 a = ((const float4*)g_as1)[g_colsrc[i]];
        pm.x = fmaxf(pm.x, lrelu(a.x + adv.x));
        pm.y = fmaxf(pm.y, lrelu(a.y + adv.y));
        pm.z = fmaxf(pm.z, lrelu(a.z + adv.z));
        pm.w = fmaxf(pm.w, lrelu(a.w + adv.w));
    }
    pm.x = wmax(pm.x); pm.y = wmax(pm.y); pm.z = wmax(pm.z); pm.w = wmax(pm.w);
    if (l == 0) s_red[w] = pm;
    __syncthreads();
    if (t == 0) {
        float4 m = s_red[0];
#pragma unroll
        for (int k = 1; k < 4; k++) {
            float4 r = s_red[k];
            m.x = fmaxf(m.x, r.x); m.y = fmaxf(m.y, r.y);
            m.z = fmaxf(m.z, r.z); m.w = fmaxf(m.w, r.w);
        }
        s_bc[0] = m;
    }
    __syncthreads();
    float4 mx = s_bc[0];

    // pass 2: denominator
    float4 pd = make_float4(0.f, 0.f, 0.f, 0.f);
    for (int i = beg + t; i < end; i += 128) {
        float4 a = ((const float4*)g_as1)[g_colsrc[i]];
        pd.x += __expf(lrelu(a.x + adv.x) - mx.x);
        pd.y += __expf(lrelu(a.y + adv.y) - mx.y);
        pd.z += __expf(lrelu(a.z + adv.z) - mx.z);
        pd.w += __expf(lrelu(a.w + adv.w) - mx.w);
    }
    pd.x = wsum(pd.x); pd.y = wsum(pd.y); pd.z = wsum(pd.z); pd.w = wsum(pd.w);
    if (l == 0) s_red[w] = pd;
    __syncthreads();
    if (t == 0) {
        float4 s = s_red[0];
#pragma unroll
        for (int k = 1; k < 4; k++) {
            float4 r = s_red[k];
            s.x += r.x; s.y += r.y; s.z += r.z; s.w += r.w;
        }
        s_bc[1] = make_float4(1.f / s.x, 1.f / s.y, 1.f / s.z, 1.f / s.w);
    }
    __syncthreads();
    float4 inv = s_bc[1];
    // this thread's head
    float mxh  = (w == 0) ? mx.x  : (w == 1) ? mx.y  : (w == 2) ? mx.z  : mx.w;
    float invh = (w == 0) ? inv.x : (w == 1) ? inv.y : (w == 2) ? inv.z : inv.w;
    float advh = (w == 0) ? adv.x : (w == 1) ? adv.y : (w == 2) ? adv.z : adv.w;

    // pass 3: weighted gather, accumulate in registers
    float4 acc = make_float4(0.f, 0.f, 0.f, 0.f);
    for (int i = beg; i < end; i++) {
        int s = g_colsrc[i];
        float al = __expf(lrelu(g_as1[s * 4 + w] + advh) - mxh) * invh;
        float4 v = ((const float4*)(g_h1 + (size_t)s * D1))[t];
        acc.x += al * v.x; acc.y += al * v.y; acc.z += al * v.z; acc.w += al * v.w;
    }
    float4 b = ((const float4*)b1)[t];
    acc.x = elu(acc.x + b.x); acc.y = elu(acc.y + b.y);
    acc.z = elu(acc.z + b.z); acc.w = elu(acc.w + b.w);
    ((float4*)(g_out1 + (size_t)d * D1))[t] = acc;
}

// ---------------- fused layer-2 aggregation + pool (warp per dst node) -------
__global__ __launch_bounds__(128) void gat_agg2(const float* __restrict__ b2,
                                                const int* __restrict__ batch) {
    int gw = (blockIdx.x * blockDim.x + threadIdx.x) >> 5;
    int l = threadIdx.x & 31;
    if (gw >= NND) return;
    int d = gw;
    int beg = g_rowptr[d], end = g_rowptr[d + 1];
    float adv = g_ad2[d];

    float mx = -1e30f;
    for (int i = beg + l; i < end; i += 32)
        mx = fmaxf(mx, lrelu(g_as2[g_colsrc[i]] + adv));
    mx = wmax(mx);

    float den = 0.f;
    for (int i = beg + l; i < end; i += 32)
        den += __expf(lrelu(g_as2[g_colsrc[i]] + adv) - mx);
    den = wsum(den);
    float inv = 1.f / den;

    float4 acc = make_float4(0.f, 0.f, 0.f, 0.f);
    for (int i = beg; i < end; i++) {
        int s = g_colsrc[i];
        float al = __expf(lrelu(g_as2[s] + adv) - mx) * inv;
        float4 v = ((const float4*)(g_h2 + (size_t)s * HID))[l];
        acc.x += al * v.x; acc.y += al * v.y; acc.z += al * v.z; acc.w += al * v.w;
    }
    float4 b = ((const float4*)b2)[l];
    acc.x = elu(acc.x + b.x); acc.y = elu(acc.y + b.y);
    acc.z = elu(acc.z + b.z); acc.w = elu(acc.w + b.w);
    int g = batch[d];
    atomicAdd((float4*)(g_pool + g * HID) + l, acc);
}

// ---------------- counts + final ----------------
__global__ void cnt_kernel(const int* __restrict__ batch) {
    int n = blockIdx.x * blockDim.x + threadIdx.x;
    if (n < NND) atomicAdd(&g_cnt[batch[n]], 1.0f);
}
__global__ void final_kernel(const float* __restrict__ Wl, const float* __restrict__ bl,
                             float* __restrict__ out) {
    int gw = (blockIdx.x * blockDim.x + threadIdx.x) >> 5;
    int l = threadIdx.x & 31;
    if (gw >= GG) return;
    float4 p = ((const float4*)g_pool)[gw * 32 + l];
    float4 w = ((const float4*)Wl)[l];
    float s = p.x * w.x + p.y * w.y + p.z * w.z + p.w * w.w;
    s = wsum(s);
    if (l == 0) out[gw] = s / fmaxf(g_cnt[gw], 1.0f) + bl[0];
}

// ---------------- launch ----------------
extern "C" void kernel_launch(void* const* d_in, const int* in_sizes, int n_in,
                              void* d_out, int out_size) {
    const float* x   = (const float*)d_in[0];
    const int*   ei  = (const int*)d_in[1];
    const int*   bat = (const int*)d_in[2];
    const float* W1  = (const float*)d_in[3];
    const float* as1 = (const float*)d_in[4];
    const float* ad1 = (const float*)d_in[5];
    const float* b1  = (const float*)d_in[6];
    const float* W2  = (const float*)d_in[7];
    const float* as2 = (const float*)d_in[8];
    const float* ad2 = (const float*)d_in[9];
    const float* b2  = (const float*)d_in[10];
    const float* Wl  = (const float*)d_in[11];
    const float* bl  = (const float*)d_in[12];
    float* out = (float*)d_out;
    const int* src = ei;
    const int* dst = ei + EE;

    float *p_h1, *p_out1, *p_h2;
    cudaGetSymbolAddress((void**)&p_h1, g_h1);
    cudaGetSymbolAddress((void**)&p_out1, g_out1);
    cudaGetSymbolAddress((void**)&p_h2, g_h2);

    int eb = (ET + 255) / 256;
    int nscan = (NND + 511) / 512;

    zero_misc<<<(GG * HID + 255) / 256 > (NND + 255) / 256 ? (GG * HID + 255) / 256
                                                           : (NND + 255) / 256, 256>>>();
    // CSR build
    deg_kernel<<<eb, 256>>>(dst);
    scanA<<<nscan, 512>>>();
    scanB<<<1, 32>>>(nscan);
    scanC<<<nscan, 512>>>();
    scatter_kernel<<<eb, 256>>>(src, dst);

    // Layer 1
    sgemm<<<dim3(D1 / BN, (NND + BM - 1) / BM), 256>>>(x, W1, p_h1, NND, D1, FIN);
    scores1<<<NND, 128>>>(as1, ad1);
    gat_agg1<<<NND, 128>>>(b1);

    // Layer 2
    sgemm<<<dim3(HID / BN, (NND + BM - 1) / BM), 256>>>(p_out1, W2, p_h2, NND, HID, D1);
    scores2<<<(NND * 32 + 127) / 128, 128>>>(as2, ad2);
    gat_agg2<<<(NND * 32 + 127) / 128, 128>>>(b2, bat);

    cnt_kernel<<<(NND + 255) / 256, 256>>>(bat);
    final_kernel<<<(GG * 32 + 255) / 256, 256>>>(Wl, bl, out);
}